// round 1
// baseline (speedup 1.0000x reference)
#include <cuda_runtime.h>
#include <math.h>
#include <stdint.h>

#define B_  2
#define S_  2048
#define D_  1024
#define H_  16
#define DH_ 64
#define MROWS (B_ * S_)   // 4096

// Scratch (allocation-free rule: __device__ globals)
__device__ float g_q[MROWS * D_];
__device__ float g_k[MROWS * D_];
__device__ float g_v[MROWS * D_];
__device__ float g_o[MROWS * D_];

// ---------------------------------------------------------------------------
// proj_gemm: C[M,N] = A[M,K] @ W[N,K]^T + bias[N]
// 128x128 block tile, BK=8, 256 threads, 8x8 per thread.
// ---------------------------------------------------------------------------
__global__ void __launch_bounds__(256) proj_gemm(
    const float* __restrict__ A,
    const float* __restrict__ W,
    const float* __restrict__ bias,
    float* __restrict__ C,
    int M, int N, int K)
{
    __shared__ float As[8][128];
    __shared__ float Bs[8][128];

    const int tid = threadIdx.x;
    const int m0 = blockIdx.y * 128;
    const int n0 = blockIdx.x * 128;
    const int tx = tid & 15;         // n subtile
    const int ty = tid >> 4;         // m subtile

    const int lr = tid >> 1;         // 0..127 tile row for loads
    const int lc = (tid & 1) * 4;    // 0 or 4

    float acc[8][8];
#pragma unroll
    for (int i = 0; i < 8; i++)
#pragma unroll
        for (int j = 0; j < 8; j++) acc[i][j] = 0.0f;

    for (int k0 = 0; k0 < K; k0 += 8) {
        float4 av = *(const float4*)&A[(size_t)(m0 + lr) * K + k0 + lc];
        float4 bv = *(const float4*)&W[(size_t)(n0 + lr) * K + k0 + lc];
        As[lc + 0][lr] = av.x; As[lc + 1][lr] = av.y;
        As[lc + 2][lr] = av.z; As[lc + 3][lr] = av.w;
        Bs[lc + 0][lr] = bv.x; Bs[lc + 1][lr] = bv.y;
        Bs[lc + 2][lr] = bv.z; Bs[lc + 3][lr] = bv.w;
        __syncthreads();

#pragma unroll
        for (int kk = 0; kk < 8; kk++) {
            float a[8], b[8];
            *(float4*)&a[0] = *(const float4*)&As[kk][ty * 8];
            *(float4*)&a[4] = *(const float4*)&As[kk][ty * 8 + 4];
            *(float4*)&b[0] = *(const float4*)&Bs[kk][tx * 8];
            *(float4*)&b[4] = *(const float4*)&Bs[kk][tx * 8 + 4];
#pragma unroll
            for (int i = 0; i < 8; i++)
#pragma unroll
                for (int j = 0; j < 8; j++)
                    acc[i][j] += a[i] * b[j];
        }
        __syncthreads();
    }

#pragma unroll
    for (int i = 0; i < 8; i++) {
        int m = m0 + ty * 8 + i;
        float* cr = C + (size_t)m * N;
#pragma unroll
        for (int jg = 0; jg < 2; jg++) {
            int n = n0 + tx * 8 + jg * 4;
            float4 o;
            o.x = acc[i][jg * 4 + 0] + bias[n + 0];
            o.y = acc[i][jg * 4 + 1] + bias[n + 1];
            o.z = acc[i][jg * 4 + 2] + bias[n + 2];
            o.w = acc[i][jg * 4 + 3] + bias[n + 3];
            *(float4*)&cr[n] = o;
        }
    }
}

// ---------------------------------------------------------------------------
// scores_gemm: per (b,h): Wout[b,h,q,k] = mask ? scale * Qh[q,:]·Kh[k,:] : -inf
// Qh/Kh are [S,DH] slices with row stride D. K-dim = DH = 64.
// 128x128 tile, BK=8, 256 threads, 8x8 per thread.
// ---------------------------------------------------------------------------
__global__ void __launch_bounds__(256) scores_gemm(
    const float* __restrict__ Qp,
    const float* __restrict__ Kp,
    const int* __restrict__ mask,
    float* __restrict__ Wout)
{
    const int bh = blockIdx.z;
    const int b = bh >> 4;
    const int h = bh & 15;

    const float* A  = Qp + (size_t)b * S_ * D_ + h * DH_;
    const float* Bm = Kp + (size_t)b * S_ * D_ + h * DH_;
    const int*  mk = mask + (size_t)b * S_ * S_;
    float* C = Wout + (size_t)bh * S_ * S_;

    __shared__ float As[8][128];
    __shared__ float Bs[8][128];

    const int tid = threadIdx.x;
    const int m0 = blockIdx.y * 128;
    const int n0 = blockIdx.x * 128;
    const int tx = tid & 15;
    const int ty = tid >> 4;
    const int lr = tid >> 1;
    const int lc = (tid & 1) * 4;

    float acc[8][8];
#pragma unroll
    for (int i = 0; i < 8; i++)
#pragma unroll
        for (int j = 0; j < 8; j++) acc[i][j] = 0.0f;

    for (int k0 = 0; k0 < DH_; k0 += 8) {
        float4 av = *(const float4*)&A[(size_t)(m0 + lr) * D_ + k0 + lc];
        float4 bv = *(const float4*)&Bm[(size_t)(n0 + lr) * D_ + k0 + lc];
        As[lc + 0][lr] = av.x; As[lc + 1][lr] = av.y;
        As[lc + 2][lr] = av.z; As[lc + 3][lr] = av.w;
        Bs[lc + 0][lr] = bv.x; Bs[lc + 1][lr] = bv.y;
        Bs[lc + 2][lr] = bv.z; Bs[lc + 3][lr] = bv.w;
        __syncthreads();

#pragma unroll
        for (int kk = 0; kk < 8; kk++) {
            float a[8], bb[8];
            *(float4*)&a[0]  = *(const float4*)&As[kk][ty * 8];
            *(float4*)&a[4]  = *(const float4*)&As[kk][ty * 8 + 4];
            *(float4*)&bb[0] = *(const float4*)&Bs[kk][tx * 8];
            *(float4*)&bb[4] = *(const float4*)&Bs[kk][tx * 8 + 4];
#pragma unroll
            for (int i = 0; i < 8; i++)
#pragma unroll
                for (int j = 0; j < 8; j++)
                    acc[i][j] += a[i] * bb[j];
        }
        __syncthreads();
    }

    const float scale = 0.125f;  // 1/sqrt(64)
#pragma unroll
    for (int i = 0; i < 8; i++) {
        int m = m0 + ty * 8 + i;
        const int* mr = mk + (size_t)m * S_;
        float* cr = C + (size_t)m * S_;
#pragma unroll
        for (int jg = 0; jg < 2; jg++) {
            int n = n0 + tx * 8 + jg * 4;
            int4 mv = *(const int4*)&mr[n];
            float4 o;
            o.x = mv.x ? acc[i][jg * 4 + 0] * scale : -INFINITY;
            o.y = mv.y ? acc[i][jg * 4 + 1] * scale : -INFINITY;
            o.z = mv.z ? acc[i][jg * 4 + 2] * scale : -INFINITY;
            o.w = mv.w ? acc[i][jg * 4 + 3] * scale : -INFINITY;
            *(float4*)&cr[n] = o;
        }
    }
}

// ---------------------------------------------------------------------------
// softmax_kernel: in-place row softmax over last dim (S=2048), 1 block/row.
// ---------------------------------------------------------------------------
__global__ void __launch_bounds__(256) softmax_kernel(float* __restrict__ Wt)
{
    const size_t row = blockIdx.x;
    float* p = Wt + row * S_;
    const int tid = threadIdx.x;

    float vals[8];
    float m = -INFINITY;
#pragma unroll
    for (int t = 0; t < 8; t++) {
        vals[t] = p[tid + t * 256];
        m = fmaxf(m, vals[t]);
    }

    __shared__ float red[256];
    red[tid] = m;
    __syncthreads();
#pragma unroll
    for (int s = 128; s > 0; s >>= 1) {
        if (tid < s) red[tid] = fmaxf(red[tid], red[tid + s]);
        __syncthreads();
    }
    m = red[0];
    __syncthreads();

    float sum = 0.0f;
#pragma unroll
    for (int t = 0; t < 8; t++) {
        vals[t] = __expf(vals[t] - m);
        sum += vals[t];
    }
    red[tid] = sum;
    __syncthreads();
#pragma unroll
    for (int s = 128; s > 0; s >>= 1) {
        if (tid < s) red[tid] += red[tid + s];
        __syncthreads();
    }
    const float inv = 1.0f / red[0];

#pragma unroll
    for (int t = 0; t < 8; t++)
        p[tid + t * 256] = vals[t] * inv;
}

// ---------------------------------------------------------------------------
// av_gemm: per (b,h): O[b, m, h*64+n] = sum_k Wt[b,h,m,k] * Vh[b,k,h*64+n]
// M=S, N=64, K=S. BM=128, BN=64, BK=16, 256 threads, 8x4 per thread.
// ---------------------------------------------------------------------------
__global__ void __launch_bounds__(256) av_gemm(
    const float* __restrict__ Wt,
    const float* __restrict__ Vp,
    float* __restrict__ O)
{
    const int bh = blockIdx.z;
    const int b = bh >> 4;
    const int h = bh & 15;

    const float* A  = Wt + (size_t)bh * S_ * S_;                 // [S,S]
    const float* Bv = Vp + (size_t)b * S_ * D_ + h * DH_;        // rows stride D
    float* C = O + (size_t)b * S_ * D_ + h * DH_;

    __shared__ float As[16][128];
    __shared__ float Bs[16][64];

    const int tid = threadIdx.x;
    const int m0 = blockIdx.x * 128;
    const int tx = tid & 15;    // n: 4 each -> 64
    const int ty = tid >> 4;    // m: 8 each -> 128

    float acc[8][4];
#pragma unroll
    for (int i = 0; i < 8; i++)
#pragma unroll
        for (int j = 0; j < 4; j++) acc[i][j] = 0.0f;

    for (int k0 = 0; k0 < S_; k0 += 16) {
        // A tile: 128 rows x 16 k = 512 float4, 2 per thread, transposed into As
#pragma unroll
        for (int t = 0; t < 2; t++) {
            int i = tid + t * 256;
            int r = i >> 2;
            int c = (i & 3) * 4;
            float4 av = *(const float4*)&A[(size_t)(m0 + r) * S_ + k0 + c];
            As[c + 0][r] = av.x; As[c + 1][r] = av.y;
            As[c + 2][r] = av.z; As[c + 3][r] = av.w;
        }
        // B tile: 16 rows x 64 n = 256 float4, 1 per thread
        {
            int r = tid >> 4;
            int c = (tid & 15) * 4;
            *(float4*)&Bs[r][c] = *(const float4*)&Bv[(size_t)(k0 + r) * D_ + c];
        }
        __syncthreads();

#pragma unroll
        for (int kk = 0; kk < 16; kk++) {
            float a[8], bb[4];
            *(float4*)&a[0]  = *(const float4*)&As[kk][ty * 8];
            *(float4*)&a[4]  = *(const float4*)&As[kk][ty * 8 + 4];
            *(float4*)&bb[0] = *(const float4*)&Bs[kk][tx * 4];
#pragma unroll
            for (int i = 0; i < 8; i++)
#pragma unroll
                for (int j = 0; j < 4; j++)
                    acc[i][j] += a[i] * bb[j];
        }
        __syncthreads();
    }

#pragma unroll
    for (int i = 0; i < 8; i++) {
        int m = m0 + ty * 8 + i;
        float4 o;
        o.x = acc[i][0]; o.y = acc[i][1]; o.z = acc[i][2]; o.w = acc[i][3];
        *(float4*)&C[(size_t)m * D_ + tx * 4] = o;
    }
}

// ---------------------------------------------------------------------------
extern "C" void kernel_launch(void* const* d_in, const int* in_sizes, int n_in,
                              void* d_out, int out_size)
{
    const float* q      = (const float*)d_in[0];
    const float* k      = (const float*)d_in[1];
    const float* v      = (const float*)d_in[2];
    const int*   mask   = (const int*)  d_in[3];
    const float* wq_w   = (const float*)d_in[4];
    const float* wq_b   = (const float*)d_in[5];
    const float* wk_w   = (const float*)d_in[6];
    const float* wk_b   = (const float*)d_in[7];
    const float* wv_w   = (const float*)d_in[8];
    const float* wv_b   = (const float*)d_in[9];
    const float* dw     = (const float*)d_in[10];
    const float* db     = (const float*)d_in[11];

    float* out = (float*)d_out;                        // [B,S,D]
    float* wts = out + (size_t)B_ * S_ * D_;           // [B,H,S,S]

    float *gq, *gk, *gv, *go;
    cudaGetSymbolAddress((void**)&gq, g_q);
    cudaGetSymbolAddress((void**)&gk, g_k);
    cudaGetSymbolAddress((void**)&gv, g_v);
    cudaGetSymbolAddress((void**)&go, g_o);

    dim3 blk(256);
    dim3 gp(D_ / 128, MROWS / 128);          // (8, 32)
    proj_gemm<<<gp, blk>>>(q, wq_w, wq_b, gq, MROWS, D_, D_);
    proj_gemm<<<gp, blk>>>(k, wk_w, wk_b, gk, MROWS, D_, D_);
    proj_gemm<<<gp, blk>>>(v, wv_w, wv_b, gv, MROWS, D_, D_);

    dim3 gs(S_ / 128, S_ / 128, B_ * H_);    // (16, 16, 32)
    scores_gemm<<<gs, blk>>>(gq, gk, mask, wts);

    softmax_kernel<<<B_ * H_ * S_, blk>>>(wts);

    dim3 ga(S_ / 128, 1, B_ * H_);           // (16, 1, 32)
    av_gemm<<<ga, blk>>>(wts, gv, go);

    proj_gemm<<<gp, blk>>>(go, dw, db, out, MROWS, D_, D_);
}

// round 4
// speedup vs baseline: 1.3572x; 1.3572x over previous
#include <cuda_runtime.h>
#include <cuda_fp16.h>
#include <math.h>
#include <stdint.h>

#define B_  2
#define S_  2048
#define D_  1024
#define H_  16
#define DH_ 64
#define MROWS (B_ * S_)   // 4096

// ---------------------------------------------------------------------------
// Scratch (allocation-free rule: __device__ globals)
// ---------------------------------------------------------------------------
__device__ float g_q[MROWS * D_];
__device__ float g_k[MROWS * D_];
__device__ float g_v[MROWS * D_];
__device__ float g_o[MROWS * D_];
__device__ __half g_ah[MROWS * D_];
__device__ __half g_al[MROWS * D_];
__device__ __half g_wh[D_ * D_];
__device__ __half g_wl[D_ * D_];

__device__ __forceinline__ uint32_t smem_to_u32(const void* p) {
    uint32_t addr;
    asm("{ .reg .u64 tmp; cvta.to.shared.u64 tmp, %1; cvt.u32.u64 %0, tmp; }"
        : "=r"(addr) : "l"(p));
    return addr;
}

// ---------------------------------------------------------------------------
// split_fp16: x (fp32) -> hi = fp16(x), lo = fp16(x - hi). Vectorized by 4.
// ---------------------------------------------------------------------------
__global__ void __launch_bounds__(256) split_fp16(
    const float* __restrict__ x,
    __half* __restrict__ hi,
    __half* __restrict__ lo,
    int n4)
{
    int i = blockIdx.x * 256 + threadIdx.x;
    if (i >= n4) return;
    float4 v = ((const float4*)x)[i];
    __half h0 = __float2half_rn(v.x);
    __half h1 = __float2half_rn(v.y);
    __half h2 = __float2half_rn(v.z);
    __half h3 = __float2half_rn(v.w);
    __half l0 = __float2half_rn(v.x - __half2float(h0));
    __half l1 = __float2half_rn(v.y - __half2float(h1));
    __half l2 = __float2half_rn(v.z - __half2float(h2));
    __half l3 = __float2half_rn(v.w - __half2float(h3));
    ((__half2*)hi)[i * 2 + 0] = __halves2half2(h0, h1);
    ((__half2*)hi)[i * 2 + 1] = __halves2half2(h2, h3);
    ((__half2*)lo)[i * 2 + 0] = __halves2half2(l0, l1);
    ((__half2*)lo)[i * 2 + 1] = __halves2half2(l2, l3);
}

// ---------------------------------------------------------------------------
// mma_proj: C[4096,1024] = A[4096,1024] @ W[1024,1024]^T + bias
// Split-fp16 3-term emulation on mma.sync.m16n8k16 (HMMA), fp32 accum.
// Block tile 128x128, BK=32, 8 warps (2x4), warp tile 64x32.
// W is [N,K] row-major = col-major B for mma.row.col -> ldmatrix WITHOUT trans.
// ---------------------------------------------------------------------------
#define PROJ_K 1024
#define SPAD 40   // halves per smem row (80B, 16B-aligned)

__device__ __forceinline__ void mma16816(float* d, const uint32_t* a, const uint32_t* b) {
    asm volatile(
        "mma.sync.aligned.m16n8k16.row.col.f32.f16.f16.f32 "
        "{%0,%1,%2,%3}, {%4,%5,%6,%7}, {%8,%9}, {%0,%1,%2,%3};"
        : "+f"(d[0]), "+f"(d[1]), "+f"(d[2]), "+f"(d[3])
        : "r"(a[0]), "r"(a[1]), "r"(a[2]), "r"(a[3]), "r"(b[0]), "r"(b[1]));
}

__global__ void __launch_bounds__(256) mma_proj(
    const __half* __restrict__ Ah, const __half* __restrict__ Al,
    const __half* __restrict__ Wh, const __half* __restrict__ Wl,
    const float* __restrict__ bias, float* __restrict__ C)
{
    __shared__ __half sA[2][128 * SPAD];
    __shared__ __half sW[2][128 * SPAD];

    const int tid = threadIdx.x;
    const int wid = tid >> 5;
    const int lane = tid & 31;
    const int m0 = blockIdx.y * 128;
    const int n0 = blockIdx.x * 128;
    const int wm = (wid >> 2) * 64;   // warp m offset
    const int wn = (wid & 3) * 32;    // warp n offset

    float acc[4][4][4];
#pragma unroll
    for (int i = 0; i < 4; i++)
#pragma unroll
        for (int j = 0; j < 4; j++)
#pragma unroll
            for (int r = 0; r < 4; r++) acc[i][j][r] = 0.0f;

    const uint32_t sA0 = smem_to_u32(&sA[0][0]);
    const uint32_t sA1 = smem_to_u32(&sA[1][0]);
    const uint32_t sW0 = smem_to_u32(&sW[0][0]);
    const uint32_t sW1 = smem_to_u32(&sW[1][0]);

    // ldmatrix per-lane source mapping
    const int a_row = (lane & 7) + ((lane >> 3) & 1) * 8;   // x4: m8 blocks, then k+8
    const int a_col = (lane >> 4) * 8;
    const int b_row = lane & 7;                              // x2: n rows (no trans)
    const int b_col = ((lane >> 3) & 1) * 8;                 // k halves 0 / 8

    // gmem->smem load mapping: 2 threads per 128-tile row, 16 halves each
    const int lrow = tid >> 1;
    const int lcol = (tid & 1) * 16;
    const int soff = lrow * SPAD + lcol;

    for (int k0 = 0; k0 < PROJ_K; k0 += 32) {
        const size_t ga = (size_t)(m0 + lrow) * PROJ_K + k0 + lcol;
        const size_t gw = (size_t)(n0 + lrow) * PROJ_K + k0 + lcol;
        __syncthreads();
        *(uint4*)&sA[0][soff]     = *(const uint4*)&Ah[ga];
        *(uint4*)&sA[0][soff + 8] = *(const uint4*)&Ah[ga + 8];
        *(uint4*)&sA[1][soff]     = *(const uint4*)&Al[ga];
        *(uint4*)&sA[1][soff + 8] = *(const uint4*)&Al[ga + 8];
        *(uint4*)&sW[0][soff]     = *(const uint4*)&Wh[gw];
        *(uint4*)&sW[0][soff + 8] = *(const uint4*)&Wh[gw + 8];
        *(uint4*)&sW[1][soff]     = *(const uint4*)&Wl[gw];
        *(uint4*)&sW[1][soff + 8] = *(const uint4*)&Wl[gw + 8];
        __syncthreads();

#pragma unroll
        for (int ks = 0; ks < 2; ks++) {
            uint32_t afh[4][4], afl[4][4], bfh[4][2], bfl[4][2];
#pragma unroll
            for (int mf = 0; mf < 4; mf++) {
                uint32_t off = (uint32_t)((wm + mf * 16 + a_row) * SPAD + ks * 16 + a_col) * 2;
                asm volatile("ldmatrix.sync.aligned.m8n8.x4.shared.b16 {%0,%1,%2,%3}, [%4];"
                    : "=r"(afh[mf][0]), "=r"(afh[mf][1]), "=r"(afh[mf][2]), "=r"(afh[mf][3])
                    : "r"(sA0 + off));
                asm volatile("ldmatrix.sync.aligned.m8n8.x4.shared.b16 {%0,%1,%2,%3}, [%4];"
                    : "=r"(afl[mf][0]), "=r"(afl[mf][1]), "=r"(afl[mf][2]), "=r"(afl[mf][3])
                    : "r"(sA1 + off));
            }
#pragma unroll
            for (int nf = 0; nf < 4; nf++) {
                uint32_t off = (uint32_t)((wn + nf * 8 + b_row) * SPAD + ks * 16 + b_col) * 2;
                asm volatile("ldmatrix.sync.aligned.m8n8.x2.shared.b16 {%0,%1}, [%2];"
                    : "=r"(bfh[nf][0]), "=r"(bfh[nf][1]) : "r"(sW0 + off));
                asm volatile("ldmatrix.sync.aligned.m8n8.x2.shared.b16 {%0,%1}, [%2];"
                    : "=r"(bfl[nf][0]), "=r"(bfl[nf][1]) : "r"(sW1 + off));
            }
#pragma unroll
            for (int mf = 0; mf < 4; mf++)
#pragma unroll
                for (int nf = 0; nf < 4; nf++) {
                    mma16816(acc[mf][nf], afh[mf], bfh[nf]);   // hi*hi
                    mma16816(acc[mf][nf], afh[mf], bfl[nf]);   // hi*lo
                    mma16816(acc[mf][nf], afl[mf], bfh[nf]);   // lo*hi
                }
        }
    }

    // Epilogue: c0:(g,2t) c1:(g,2t+1) c2:(g+8,2t) c3:(g+8,2t+1)
    const int g = lane >> 2;
    const int t = lane & 3;
#pragma unroll
    for (int mf = 0; mf < 4; mf++) {
#pragma unroll
        for (int nf = 0; nf < 4; nf++) {
            const int col = n0 + wn + nf * 8 + t * 2;
            const float b0 = bias[col], b1 = bias[col + 1];
            const int row = m0 + wm + mf * 16 + g;
            float2 o0, o1;
            o0.x = acc[mf][nf][0] + b0; o0.y = acc[mf][nf][1] + b1;
            o1.x = acc[mf][nf][2] + b0; o1.y = acc[mf][nf][3] + b1;
            *(float2*)&C[(size_t)row * D_ + col] = o0;
            *(float2*)&C[(size_t)(row + 8) * D_ + col] = o1;
        }
    }
}

// ---------------------------------------------------------------------------
// scores_gemm: per (b,h): Wout[b,h,q,k] = mask ? scale * Qh[q,:]·Kh[k,:] : -inf
// ---------------------------------------------------------------------------
__global__ void __launch_bounds__(256) scores_gemm(
    const float* __restrict__ Qp,
    const float* __restrict__ Kp,
    const int* __restrict__ mask,
    float* __restrict__ Wout)
{
    const int bh = blockIdx.z;
    const int b = bh >> 4;
    const int h = bh & 15;

    const float* A  = Qp + (size_t)b * S_ * D_ + h * DH_;
    const float* Bm = Kp + (size_t)b * S_ * D_ + h * DH_;
    const int*  mk = mask + (size_t)b * S_ * S_;
    float* C = Wout + (size_t)bh * S_ * S_;

    __shared__ float As[8][128];
    __shared__ float Bs[8][128];

    const int tid = threadIdx.x;
    const int m0 = blockIdx.y * 128;
    const int n0 = blockIdx.x * 128;
    const int tx = tid & 15;
    const int ty = tid >> 4;
    const int lr = tid >> 1;
    const int lc = (tid & 1) * 4;

    float acc[8][8];
#pragma unroll
    for (int i = 0; i < 8; i++)
#pragma unroll
        for (int j = 0; j < 8; j++) acc[i][j] = 0.0f;

    for (int k0 = 0; k0 < DH_; k0 += 8) {
        float4 av = *(const float4*)&A[(size_t)(m0 + lr) * D_ + k0 + lc];
        float4 bv = *(const float4*)&Bm[(size_t)(n0 + lr) * D_ + k0 + lc];
        As[lc + 0][lr] = av.x; As[lc + 1][lr] = av.y;
        As[lc + 2][lr] = av.z; As[lc + 3][lr] = av.w;
        Bs[lc + 0][lr] = bv.x; Bs[lc + 1][lr] = bv.y;
        Bs[lc + 2][lr] = bv.z; Bs[lc + 3][lr] = bv.w;
        __syncthreads();

#pragma unroll
        for (int kk = 0; kk < 8; kk++) {
            float a[8], bb[8];
            *(float4*)&a[0]  = *(const float4*)&As[kk][ty * 8];
            *(float4*)&a[4]  = *(const float4*)&As[kk][ty * 8 + 4];
            *(float4*)&bb[0] = *(const float4*)&Bs[kk][tx * 8];
            *(float4*)&bb[4] = *(const float4*)&Bs[kk][tx * 8 + 4];
#pragma unroll
            for (int i = 0; i < 8; i++)
#pragma unroll
                for (int j = 0; j < 8; j++)
                    acc[i][j] += a[i] * bb[j];
        }
        __syncthreads();
    }

    const float scale = 0.125f;
#pragma unroll
    for (int i = 0; i < 8; i++) {
        int m = m0 + ty * 8 + i;
        const int* mr = mk + (size_t)m * S_;
        float* cr = C + (size_t)m * S_;
#pragma unroll
        for (int jg = 0; jg < 2; jg++) {
            int n = n0 + tx * 8 + jg * 4;
            int4 mv = *(const int4*)&mr[n];
            float4 o;
            o.x = mv.x ? acc[i][jg * 4 + 0] * scale : -INFINITY;
            o.y = mv.y ? acc[i][jg * 4 + 1] * scale : -INFINITY;
            o.z = mv.z ? acc[i][jg * 4 + 2] * scale : -INFINITY;
            o.w = mv.w ? acc[i][jg * 4 + 3] * scale : -INFINITY;
            *(float4*)&cr[n] = o;
        }
    }
}

// ---------------------------------------------------------------------------
// softmax_kernel: in-place row softmax over last dim (S=2048), 1 block/row.
// ---------------------------------------------------------------------------
__global__ void __launch_bounds__(256) softmax_kernel(float* __restrict__ Wt)
{
    const size_t row = blockIdx.x;
    float* p = Wt + row * S_;
    const int tid = threadIdx.x;

    float vals[8];
    float m = -INFINITY;
#pragma unroll
    for (int t = 0; t < 8; t++) {
        vals[t] = p[tid + t * 256];
        m = fmaxf(m, vals[t]);
    }

    __shared__ float red[256];
    red[tid] = m;
    __syncthreads();
#pragma unroll
    for (int s = 128; s > 0; s >>= 1) {
        if (tid < s) red[tid] = fmaxf(red[tid], red[tid + s]);
        __syncthreads();
    }
    m = red[0];
    __syncthreads();

    float sum = 0.0f;
#pragma unroll
    for (int t = 0; t < 8; t++) {
        vals[t] = __expf(vals[t] - m);
        sum += vals[t];
    }
    red[tid] = sum;
    __syncthreads();
#pragma unroll
    for (int s = 128; s > 0; s >>= 1) {
        if (tid < s) red[tid] += red[tid + s];
        __syncthreads();
    }
    const float inv = 1.0f / red[0];

#pragma unroll
    for (int t = 0; t < 8; t++)
        p[tid + t * 256] = vals[t] * inv;
}

// ---------------------------------------------------------------------------
// av_gemm: per (b,h): O[b, m, h*64+n] = sum_k Wt[b,h,m,k] * Vh[b,k,h*64+n]
// ---------------------------------------------------------------------------
__global__ void __launch_bounds__(256) av_gemm(
    const float* __restrict__ Wt,
    const float* __restrict__ Vp,
    float* __restrict__ O)
{
    const int bh = blockIdx.z;
    const int b = bh >> 4;
    const int h = bh & 15;

    const float* A  = Wt + (size_t)bh * S_ * S_;
    const float* Bv = Vp + (size_t)b * S_ * D_ + h * DH_;
    float* C = O + (size_t)b * S_ * D_ + h * DH_;

    __shared__ float As[16][128];
    __shared__ float Bs[16][64];

    const int tid = threadIdx.x;
    const int m0 = blockIdx.x * 128;
    const int tx = tid & 15;
    const int ty = tid >> 4;

    float acc[8][4];
#pragma unroll
    for (int i = 0; i < 8; i++)
#pragma unroll
        for (int j = 0; j < 4; j++) acc[i][j] = 0.0f;

    for (int k0 = 0; k0 < S_; k0 += 16) {
#pragma unroll
        for (int t = 0; t < 2; t++) {
            int i = tid + t * 256;
            int r = i >> 2;
            int c = (i & 3) * 4;
            float4 av = *(const float4*)&A[(size_t)(m0 + r) * S_ + k0 + c];
            As[c + 0][r] = av.x; As[c + 1][r] = av.y;
            As[c + 2][r] = av.z; As[c + 3][r] = av.w;
        }
        {
            int r = tid >> 4;
            int c = (tid & 15) * 4;
            *(float4*)&Bs[r][c] = *(const float4*)&Bv[(size_t)(k0 + r) * D_ + c];
        }
        __syncthreads();

#pragma unroll
        for (int kk = 0; kk < 16; kk++) {
            float a[8], bb[4];
            *(float4*)&a[0]  = *(const float4*)&As[kk][ty * 8];
            *(float4*)&a[4]  = *(const float4*)&As[kk][ty * 8 + 4];
            *(float4*)&bb[0] = *(const float4*)&Bs[kk][tx * 4];
#pragma unroll
            for (int i = 0; i < 8; i++)
#pragma unroll
                for (int j = 0; j < 4; j++)
                    acc[i][j] += a[i] * bb[j];
        }
        __syncthreads();
    }

#pragma unroll
    for (int i = 0; i < 8; i++) {
        int m = m0 + ty * 8 + i;
        float4 o;
        o.x = acc[i][0]; o.y = acc[i][1]; o.z = acc[i][2]; o.w = acc[i][3];
        *(float4*)&C[(size_t)m * D_ + tx * 4] = o;
    }
}

// ---------------------------------------------------------------------------
extern "C" void kernel_launch(void* const* d_in, const int* in_sizes, int n_in,
                              void* d_out, int out_size)
{
    const float* q      = (const float*)d_in[0];
    const float* k      = (const float*)d_in[1];
    const float* v      = (const float*)d_in[2];
    const int*   mask   = (const int*)  d_in[3];
    const float* wq_w   = (const float*)d_in[4];
    const float* wq_b   = (const float*)d_in[5];
    const float* wk_w   = (const float*)d_in[6];
    const float* wk_b   = (const float*)d_in[7];
    const float* wv_w   = (const float*)d_in[8];
    const float* wv_b   = (const float*)d_in[9];
    const float* dw     = (const float*)d_in[10];
    const float* db     = (const float*)d_in[11];

    float* out = (float*)d_out;                        // [B,S,D]
    float* wts = out + (size_t)B_ * S_ * D_;           // [B,H,S,S]

    float *gq, *gk, *gv, *go;
    cudaGetSymbolAddress((void**)&gq, g_q);
    cudaGetSymbolAddress((void**)&gk, g_k);
    cudaGetSymbolAddress((void**)&gv, g_v);
    cudaGetSymbolAddress((void**)&go, g_o);
    __half *ah, *al, *wh, *wl;
    cudaGetSymbolAddress((void**)&ah, g_ah);
    cudaGetSymbolAddress((void**)&al, g_al);
    cudaGetSymbolAddress((void**)&wh, g_wh);
    cudaGetSymbolAddress((void**)&wl, g_wl);

    const int n4A = MROWS * D_ / 4;
    const int n4W = D_ * D_ / 4;
    dim3 blk(256);
    dim3 gproj(D_ / 128, MROWS / 128);   // (8, 32)

    // Q projection
    split_fp16<<<n4A / 256, blk>>>(q, ah, al, n4A);
    split_fp16<<<n4W / 256, blk>>>(wq_w, wh, wl, n4W);
    mma_proj<<<gproj, blk>>>(ah, al, wh, wl, wq_b, gq);
    // K projection
    split_fp16<<<n4A / 256, blk>>>(k, ah, al, n4A);
    split_fp16<<<n4W / 256, blk>>>(wk_w, wh, wl, n4W);
    mma_proj<<<gproj, blk>>>(ah, al, wh, wl, wk_b, gk);
    // V projection
    split_fp16<<<n4A / 256, blk>>>(v, ah, al, n4A);
    split_fp16<<<n4W / 256, blk>>>(wv_w, wh, wl, n4W);
    mma_proj<<<gproj, blk>>>(ah, al, wh, wl, wv_b, gv);

    // Attention
    dim3 gs(S_ / 128, S_ / 128, B_ * H_);
    scores_gemm<<<gs, blk>>>(gq, gk, mask, wts);
    softmax_kernel<<<B_ * H_ * S_, blk>>>(wts);
    dim3 ga(S_ / 128, 1, B_ * H_);
    av_gemm<<<ga, blk>>>(wts, gv, go);

    // Output projection
    split_fp16<<<n4A / 256, blk>>>(go, ah, al, n4A);
    split_fp16<<<n4W / 256, blk>>>(dw, wh, wl, n4W);
    mma_proj<<<gproj, blk>>>(ah, al, wh, wl, db, out);
}

// round 5
// speedup vs baseline: 1.8107x; 1.3341x over previous
#include <cuda_runtime.h>
#include <cuda_fp16.h>
#include <math.h>
#include <stdint.h>

#define B_  2
#define S_  2048
#define D_  1024
#define H_  16
#define DH_ 64
#define MROWS (B_ * S_)   // 4096

// ---------------------------------------------------------------------------
// Scratch (allocation-free rule: __device__ globals)
// ---------------------------------------------------------------------------
__device__ __half g_ah[MROWS * D_];          // split staging of fp32 activations
__device__ __half g_al[MROWS * D_];
__device__ __half g_wwh[D_ * D_];            // split staging of weight matrix
__device__ __half g_wwl[D_ * D_];
__device__ __half g_qh[MROWS * D_];          // projected Q/K/V, hi/lo planes
__device__ __half g_ql[MROWS * D_];
__device__ __half g_kh[MROWS * D_];
__device__ __half g_kl[MROWS * D_];
__device__ __half g_vh[MROWS * D_];
__device__ __half g_vl[MROWS * D_];
__device__ __half g_oh[MROWS * D_];          // attention output, hi/lo planes
__device__ __half g_ol[MROWS * D_];
__device__ __half g_swh[(size_t)B_ * H_ * S_ * S_];   // softmax weights hi
__device__ __half g_swl[(size_t)B_ * H_ * S_ * S_];   // softmax weights lo

__device__ __forceinline__ uint32_t smem_to_u32(const void* p) {
    uint32_t addr;
    asm("{ .reg .u64 tmp; cvta.to.shared.u64 tmp, %1; cvt.u32.u64 %0, tmp; }"
        : "=r"(addr) : "l"(p));
    return addr;
}

__device__ __forceinline__ void mma16816(float* d, const uint32_t* a, const uint32_t* b) {
    asm volatile(
        "mma.sync.aligned.m16n8k16.row.col.f32.f16.f16.f32 "
        "{%0,%1,%2,%3}, {%4,%5,%6,%7}, {%8,%9}, {%0,%1,%2,%3};"
        : "+f"(d[0]), "+f"(d[1]), "+f"(d[2]), "+f"(d[3])
        : "r"(a[0]), "r"(a[1]), "r"(a[2]), "r"(a[3]), "r"(b[0]), "r"(b[1]));
}

// ---------------------------------------------------------------------------
// split_fp16: x (fp32) -> hi = fp16(x), lo = fp16(x - hi). Vectorized by 4.
// ---------------------------------------------------------------------------
__global__ void __launch_bounds__(256) split_fp16(
    const float* __restrict__ x,
    __half* __restrict__ hi,
    __half* __restrict__ lo,
    int n4)
{
    int i = blockIdx.x * 256 + threadIdx.x;
    if (i >= n4) return;
    float4 v = ((const float4*)x)[i];
    __half h0 = __float2half_rn(v.x);
    __half h1 = __float2half_rn(v.y);
    __half h2 = __float2half_rn(v.z);
    __half h3 = __float2half_rn(v.w);
    __half l0 = __float2half_rn(v.x - __half2float(h0));
    __half l1 = __float2half_rn(v.y - __half2float(h1));
    __half l2 = __float2half_rn(v.z - __half2float(h2));
    __half l3 = __float2half_rn(v.w - __half2float(h3));
    ((__half2*)hi)[i * 2 + 0] = __halves2half2(h0, h1);
    ((__half2*)hi)[i * 2 + 1] = __halves2half2(h2, h3);
    ((__half2*)lo)[i * 2 + 0] = __halves2half2(l0, l1);
    ((__half2*)lo)[i * 2 + 1] = __halves2half2(l2, l3);
}

// ---------------------------------------------------------------------------
// Shared 128x128 HMMA mainloop (split-fp16 3-term).
// A [128 rows, K] row stride lda (hi/lo), B [128 rows, K] row stride ldb (hi/lo),
// both k-contiguous -> A: ldmatrix.x4, B: ldmatrix.x2 (no trans).
// 8 warps (2x4), warp tile 64x32. BK=32.
// ---------------------------------------------------------------------------
#define SPAD 40
#define PLANE (128 * SPAD)

__device__ __forceinline__ void mainloop128(
    const __half* __restrict__ A0, const __half* __restrict__ A1,
    const __half* __restrict__ B0, const __half* __restrict__ B1,
    int lda, int ldb, int K, __half* sbase,
    float (&acc)[4][4][4])
{
    const int tid = threadIdx.x;
    const int wid = tid >> 5;
    const int lane = tid & 31;
    const int wm = (wid >> 2) * 64;
    const int wn = (wid & 3) * 32;

    __half* sA0p = sbase;
    __half* sA1p = sbase + PLANE;
    __half* sW0p = sbase + 2 * PLANE;
    __half* sW1p = sbase + 3 * PLANE;
    const uint32_t sA0 = smem_to_u32(sA0p);
    const uint32_t sA1 = smem_to_u32(sA1p);
    const uint32_t sW0 = smem_to_u32(sW0p);
    const uint32_t sW1 = smem_to_u32(sW1p);

    const int a_row = (lane & 7) + ((lane >> 3) & 1) * 8;
    const int a_col = (lane >> 4) * 8;
    const int b_row = lane & 7;
    const int b_col = ((lane >> 3) & 1) * 8;

    const int lrow = tid >> 1;
    const int lcol = (tid & 1) * 16;
    const int soff = lrow * SPAD + lcol;

    for (int k0 = 0; k0 < K; k0 += 32) {
        const size_t ga = (size_t)lrow * lda + k0 + lcol;
        const size_t gw = (size_t)lrow * ldb + k0 + lcol;
        __syncthreads();
        *(uint4*)&sA0p[soff]     = *(const uint4*)&A0[ga];
        *(uint4*)&sA0p[soff + 8] = *(const uint4*)&A0[ga + 8];
        *(uint4*)&sA1p[soff]     = *(const uint4*)&A1[ga];
        *(uint4*)&sA1p[soff + 8] = *(const uint4*)&A1[ga + 8];
        *(uint4*)&sW0p[soff]     = *(const uint4*)&B0[gw];
        *(uint4*)&sW0p[soff + 8] = *(const uint4*)&B0[gw + 8];
        *(uint4*)&sW1p[soff]     = *(const uint4*)&B1[gw];
        *(uint4*)&sW1p[soff + 8] = *(const uint4*)&B1[gw + 8];
        __syncthreads();

#pragma unroll
        for (int ks = 0; ks < 2; ks++) {
            uint32_t afh[4][4], afl[4][4], bfh[4][2], bfl[4][2];
#pragma unroll
            for (int mf = 0; mf < 4; mf++) {
                uint32_t off = (uint32_t)((wm + mf * 16 + a_row) * SPAD + ks * 16 + a_col) * 2;
                asm volatile("ldmatrix.sync.aligned.m8n8.x4.shared.b16 {%0,%1,%2,%3}, [%4];"
                    : "=r"(afh[mf][0]), "=r"(afh[mf][1]), "=r"(afh[mf][2]), "=r"(afh[mf][3])
                    : "r"(sA0 + off));
                asm volatile("ldmatrix.sync.aligned.m8n8.x4.shared.b16 {%0,%1,%2,%3}, [%4];"
                    : "=r"(afl[mf][0]), "=r"(afl[mf][1]), "=r"(afl[mf][2]), "=r"(afl[mf][3])
                    : "r"(sA1 + off));
            }
#pragma unroll
            for (int nf = 0; nf < 4; nf++) {
                uint32_t off = (uint32_t)((wn + nf * 8 + b_row) * SPAD + ks * 16 + b_col) * 2;
                asm volatile("ldmatrix.sync.aligned.m8n8.x2.shared.b16 {%0,%1}, [%2];"
                    : "=r"(bfh[nf][0]), "=r"(bfh[nf][1]) : "r"(sW0 + off));
                asm volatile("ldmatrix.sync.aligned.m8n8.x2.shared.b16 {%0,%1}, [%2];"
                    : "=r"(bfl[nf][0]), "=r"(bfl[nf][1]) : "r"(sW1 + off));
            }
#pragma unroll
            for (int mf = 0; mf < 4; mf++)
#pragma unroll
                for (int nf = 0; nf < 4; nf++) {
                    mma16816(acc[mf][nf], afh[mf], bfh[nf]);
                    mma16816(acc[mf][nf], afh[mf], bfl[nf]);
                    mma16816(acc[mf][nf], afl[mf], bfh[nf]);
                }
        }
    }
}

// ---------------------------------------------------------------------------
// proj_f32: final dense projection -> fp32 out (d_out)
// ---------------------------------------------------------------------------
__global__ void __launch_bounds__(256) proj_f32(
    const __half* __restrict__ Ah, const __half* __restrict__ Al,
    const __half* __restrict__ Wh, const __half* __restrict__ Wl,
    const float* __restrict__ bias, float* __restrict__ C)
{
    __shared__ __half smem[4 * PLANE];
    const int m0 = blockIdx.y * 128;
    const int n0 = blockIdx.x * 128;
    float acc[4][4][4] = {};
    mainloop128(Ah + (size_t)m0 * D_, Al + (size_t)m0 * D_,
                Wh + (size_t)n0 * D_, Wl + (size_t)n0 * D_,
                D_, D_, D_, smem, acc);

    const int lane = threadIdx.x & 31;
    const int wid = threadIdx.x >> 5;
    const int wm = (wid >> 2) * 64, wn = (wid & 3) * 32;
    const int g = lane >> 2, t = lane & 3;
#pragma unroll
    for (int mf = 0; mf < 4; mf++)
#pragma unroll
        for (int nf = 0; nf < 4; nf++) {
            const int col = n0 + wn + nf * 8 + t * 2;
            const float b0 = bias[col], b1 = bias[col + 1];
            const int row = m0 + wm + mf * 16 + g;
            float2 o0, o1;
            o0.x = acc[mf][nf][0] + b0; o0.y = acc[mf][nf][1] + b1;
            o1.x = acc[mf][nf][2] + b0; o1.y = acc[mf][nf][3] + b1;
            *(float2*)&C[(size_t)row * D_ + col] = o0;
            *(float2*)&C[(size_t)(row + 8) * D_ + col] = o1;
        }
}

// ---------------------------------------------------------------------------
// proj_hl: QKV projection -> hi/lo half planes directly (no fp32 pass)
// ---------------------------------------------------------------------------
__global__ void __launch_bounds__(256) proj_hl(
    const __half* __restrict__ Ah, const __half* __restrict__ Al,
    const __half* __restrict__ Wh, const __half* __restrict__ Wl,
    const float* __restrict__ bias,
    __half* __restrict__ Ch, __half* __restrict__ Cl)
{
    __shared__ __half smem[4 * PLANE];
    const int m0 = blockIdx.y * 128;
    const int n0 = blockIdx.x * 128;
    float acc[4][4][4] = {};
    mainloop128(Ah + (size_t)m0 * D_, Al + (size_t)m0 * D_,
                Wh + (size_t)n0 * D_, Wl + (size_t)n0 * D_,
                D_, D_, D_, smem, acc);

    const int lane = threadIdx.x & 31;
    const int wid = threadIdx.x >> 5;
    const int wm = (wid >> 2) * 64, wn = (wid & 3) * 32;
    const int g = lane >> 2, t = lane & 3;
#pragma unroll
    for (int mf = 0; mf < 4; mf++)
#pragma unroll
        for (int nf = 0; nf < 4; nf++) {
            const int col = n0 + wn + nf * 8 + t * 2;
            const float b0 = bias[col], b1 = bias[col + 1];
            const int row = m0 + wm + mf * 16 + g;
            float v0 = acc[mf][nf][0] + b0, v1 = acc[mf][nf][1] + b1;
            float v2 = acc[mf][nf][2] + b0, v3 = acc[mf][nf][3] + b1;
            __half h0 = __float2half_rn(v0), h1 = __float2half_rn(v1);
            __half h2 = __float2half_rn(v2), h3 = __float2half_rn(v3);
            *(__half2*)&Ch[(size_t)row * D_ + col] = __halves2half2(h0, h1);
            *(__half2*)&Ch[(size_t)(row + 8) * D_ + col] = __halves2half2(h2, h3);
            *(__half2*)&Cl[(size_t)row * D_ + col] =
                __halves2half2(__float2half_rn(v0 - __half2float(h0)),
                               __float2half_rn(v1 - __half2float(h1)));
            *(__half2*)&Cl[(size_t)(row + 8) * D_ + col] =
                __halves2half2(__float2half_rn(v2 - __half2float(h2)),
                               __float2half_rn(v3 - __half2float(h3)));
        }
}

// ---------------------------------------------------------------------------
// scores_mma: per (b,h): Wout = mask ? scale*(Q K^T) : -inf ; K-dim = 64
// ---------------------------------------------------------------------------
__global__ void __launch_bounds__(256) scores_mma(
    const __half* __restrict__ Qh, const __half* __restrict__ Ql,
    const __half* __restrict__ Kh, const __half* __restrict__ Kl,
    const int* __restrict__ mask, float* __restrict__ Wout)
{
    __shared__ __half smem[4 * PLANE];
    const int bh = blockIdx.z;
    const int b = bh >> 4;
    const int h = bh & 15;
    const int m0 = blockIdx.y * 128;
    const int n0 = blockIdx.x * 128;

    const size_t aoff = ((size_t)b * S_ + m0) * D_ + h * DH_;
    const size_t boff = ((size_t)b * S_ + n0) * D_ + h * DH_;
    float acc[4][4][4] = {};
    mainloop128(Qh + aoff, Ql + aoff, Kh + boff, Kl + boff,
                D_, D_, DH_, smem, acc);

    const int* mk = mask + (size_t)b * S_ * S_;
    float* C = Wout + (size_t)bh * S_ * S_;
    const int lane = threadIdx.x & 31;
    const int wid = threadIdx.x >> 5;
    const int wm = (wid >> 2) * 64, wn = (wid & 3) * 32;
    const int g = lane >> 2, t = lane & 3;
    const float scale = 0.125f;
#pragma unroll
    for (int mf = 0; mf < 4; mf++)
#pragma unroll
        for (int nf = 0; nf < 4; nf++) {
            const int col = n0 + wn + nf * 8 + t * 2;
#pragma unroll
            for (int rr = 0; rr < 2; rr++) {
                const int row = m0 + wm + mf * 16 + g + rr * 8;
                int2 mv = *(const int2*)&mk[(size_t)row * S_ + col];
                float2 o;
                o.x = mv.x ? acc[mf][nf][rr * 2 + 0] * scale : -INFINITY;
                o.y = mv.y ? acc[mf][nf][rr * 2 + 1] * scale : -INFINITY;
                *(float2*)&C[(size_t)row * S_ + col] = o;
            }
        }
}

// ---------------------------------------------------------------------------
// softmax_split: in-place row softmax + emit hi/lo half planes.
// ---------------------------------------------------------------------------
__global__ void __launch_bounds__(256) softmax_split(
    float* __restrict__ Wt, __half* __restrict__ Wh, __half* __restrict__ Wl)
{
    const size_t row = blockIdx.x;
    float* p = Wt + row * S_;
    __half* ph = Wh + row * S_;
    __half* pl = Wl + row * S_;
    const int tid = threadIdx.x;

    float vals[8];
    float m = -INFINITY;
#pragma unroll
    for (int t = 0; t < 8; t++) {
        vals[t] = p[tid + t * 256];
        m = fmaxf(m, vals[t]);
    }

    __shared__ float red[256];
    red[tid] = m;
    __syncthreads();
#pragma unroll
    for (int s = 128; s > 0; s >>= 1) {
        if (tid < s) red[tid] = fmaxf(red[tid], red[tid + s]);
        __syncthreads();
    }
    m = red[0];
    __syncthreads();

    float sum = 0.0f;
#pragma unroll
    for (int t = 0; t < 8; t++) {
        vals[t] = __expf(vals[t] - m);
        sum += vals[t];
    }
    red[tid] = sum;
    __syncthreads();
#pragma unroll
    for (int s = 128; s > 0; s >>= 1) {
        if (tid < s) red[tid] += red[tid + s];
        __syncthreads();
    }
    const float inv = 1.0f / red[0];

#pragma unroll
    for (int t = 0; t < 8; t++) {
        const int idx = tid + t * 256;
        const float r = vals[t] * inv;
        p[idx] = r;
        const __half h = __float2half_rn(r);
        ph[idx] = h;
        pl[idx] = __float2half_rn(r - __half2float(h));
    }
}

// ---------------------------------------------------------------------------
// av_mma: per (b,h): O[m, h*64+n] = sum_k W[m,k] V[k, h*64+n]; out as hi/lo.
// BM=128, BN=64, BK=32. 8 warps (4m x 2n), warp tile 32x32.
// A: ldmatrix.x4 (row-major, k contig). B: V[k][n] n-contig -> ldmatrix.x2.trans.
// ---------------------------------------------------------------------------
#define AV_SPAD_A 40
#define AV_SPAD_B 72

__global__ void __launch_bounds__(256) av_mma(
    const __half* __restrict__ Wh, const __half* __restrict__ Wl,
    const __half* __restrict__ Vh, const __half* __restrict__ Vl,
    __half* __restrict__ Oh, __half* __restrict__ Ol)
{
    __shared__ __half sA0p[128 * AV_SPAD_A], sA1p[128 * AV_SPAD_A];
    __shared__ __half sB0p[32 * AV_SPAD_B], sB1p[32 * AV_SPAD_B];

    const int bh = blockIdx.z;
    const int b = bh >> 4;
    const int h = bh & 15;
    const int m0 = blockIdx.x * 128;

    const __half* A0 = Wh + (size_t)bh * S_ * S_ + (size_t)m0 * S_;
    const __half* A1 = Wl + (size_t)bh * S_ * S_ + (size_t)m0 * S_;
    const __half* B0 = Vh + (size_t)b * S_ * D_ + h * DH_;
    const __half* B1 = Vl + (size_t)b * S_ * D_ + h * DH_;

    const int tid = threadIdx.x;
    const int wid = tid >> 5;
    const int lane = tid & 31;
    const int wm = (wid >> 1) * 32;
    const int wn = (wid & 1) * 32;

    float acc[2][4][4] = {};

    const uint32_t sA0 = smem_to_u32(sA0p);
    const uint32_t sA1 = smem_to_u32(sA1p);
    const uint32_t sB0 = smem_to_u32(sB0p);
    const uint32_t sB1 = smem_to_u32(sB1p);

    const int a_row = (lane & 7) + ((lane >> 3) & 1) * 8;
    const int a_col = (lane >> 4) * 8;
    const int bt_row = (lane & 7) + ((lane >> 3) & 1) * 8;  // k row within 16

    // A loads: per plane 512 uint4 (128 rows x 4), 2 per thread
    // B loads: per plane 256 uint4 (32 rows x 8), 1 per thread
    const int ar0 = tid >> 2, ac0 = (tid & 3) * 8;
    const int ar1 = (tid + 256) >> 2, ac1 = ((tid + 256) & 3) * 8;
    const int br = tid >> 3, bc = (tid & 7) * 8;

    for (int k0 = 0; k0 < S_; k0 += 32) {
        __syncthreads();
        {
            const size_t ga0 = (size_t)ar0 * S_ + k0 + ac0;
            const size_t ga1 = (size_t)ar1 * S_ + k0 + ac1;
            *(uint4*)&sA0p[ar0 * AV_SPAD_A + ac0] = *(const uint4*)&A0[ga0];
            *(uint4*)&sA0p[ar1 * AV_SPAD_A + ac1] = *(const uint4*)&A0[ga1];
            *(uint4*)&sA1p[ar0 * AV_SPAD_A + ac0] = *(const uint4*)&A1[ga0];
            *(uint4*)&sA1p[ar1 * AV_SPAD_A + ac1] = *(const uint4*)&A1[ga1];
            const size_t gb = (size_t)(k0 + br) * D_ + bc;
            *(uint4*)&sB0p[br * AV_SPAD_B + bc] = *(const uint4*)&B0[gb];
            *(uint4*)&sB1p[br * AV_SPAD_B + bc] = *(const uint4*)&B1[gb];
        }
        __syncthreads();

#pragma unroll
        for (int ks = 0; ks < 2; ks++) {
            uint32_t afh[2][4], afl[2][4], bfh[4][2], bfl[4][2];
#pragma unroll
            for (int mf = 0; mf < 2; mf++) {
                uint32_t off = (uint32_t)((wm + mf * 16 + a_row) * AV_SPAD_A + ks * 16 + a_col) * 2;
                asm volatile("ldmatrix.sync.aligned.m8n8.x4.shared.b16 {%0,%1,%2,%3}, [%4];"
                    : "=r"(afh[mf][0]), "=r"(afh[mf][1]), "=r"(afh[mf][2]), "=r"(afh[mf][3])
                    : "r"(sA0 + off));
                asm volatile("ldmatrix.sync.aligned.m8n8.x4.shared.b16 {%0,%1,%2,%3}, [%4];"
                    : "=r"(afl[mf][0]), "=r"(afl[mf][1]), "=r"(afl[mf][2]), "=r"(afl[mf][3])
                    : "r"(sA1 + off));
            }
#pragma unroll
            for (int nf = 0; nf < 4; nf++) {
                uint32_t off = (uint32_t)((ks * 16 + bt_row) * AV_SPAD_B + wn + nf * 8) * 2;
                asm volatile("ldmatrix.sync.aligned.m8n8.x2.trans.shared.b16 {%0,%1}, [%2];"
                    : "=r"(bfh[nf][0]), "=r"(bfh[nf][1]) : "r"(sB0 + off));
                asm volatile("ldmatrix.sync.aligned.m8n8.x2.trans.shared.b16 {%0,%1}, [%2];"
                    : "=r"(bfl[nf][0]), "=r"(bfl[nf][1]) : "r"(sB1 + off));
            }
#pragma unroll
            for (int mf = 0; mf < 2; mf++)
#pragma unroll
                for (int nf = 0; nf < 4; nf++) {
                    mma16816(acc[mf][nf], afh[mf], bfh[nf]);
                    mma16816(acc[mf][nf], afh[mf], bfl[nf]);
                    mma16816(acc[mf][nf], afl[mf], bfh[nf]);
                }
        }
    }

    const int g = lane >> 2, t = lane & 3;
#pragma unroll
    for (int mf = 0; mf < 2; mf++)
#pragma unroll
        for (int nf = 0; nf < 4; nf++) {
            const int col = h * DH_ + wn + nf * 8 + t * 2;
#pragma unroll
            for (int rr = 0; rr < 2; rr++) {
                const int row = m0 + wm + mf * 16 + g + rr * 8;
                const size_t o = ((size_t)b * S_ + row) * D_ + col;
                float v0 = acc[mf][nf][rr * 2 + 0];
                float v1 = acc[mf][nf][rr * 2 + 1];
                __half h0 = __float2half_rn(v0), h1 = __float2half_rn(v1);
                *(__half2*)&Oh[o] = __halves2half2(h0, h1);
                *(__half2*)&Ol[o] =
                    __halves2half2(__float2half_rn(v0 - __half2float(h0)),
                                   __float2half_rn(v1 - __half2float(h1)));
            }
        }
}

// ---------------------------------------------------------------------------
extern "C" void kernel_launch(void* const* d_in, const int* in_sizes, int n_in,
                              void* d_out, int out_size)
{
    const float* q      = (const float*)d_in[0];
    const float* k      = (const float*)d_in[1];
    const float* v      = (const float*)d_in[2];
    const int*   mask   = (const int*)  d_in[3];
    const float* wq_w   = (const float*)d_in[4];
    const float* wq_b   = (const float*)d_in[5];
    const float* wk_w   = (const float*)d_in[6];
    const float* wk_b   = (const float*)d_in[7];
    const float* wv_w   = (const float*)d_in[8];
    const float* wv_b   = (const float*)d_in[9];
    const float* dw     = (const float*)d_in[10];
    const float* db     = (const float*)d_in[11];

    float* out = (float*)d_out;                        // [B,S,D]
    float* wts = out + (size_t)B_ * S_ * D_;           // [B,H,S,S]

    __half *ah, *al, *wwh, *wwl, *qh, *ql, *kh, *kl, *vh, *vl, *oh, *ol, *swh, *swl;
    cudaGetSymbolAddress((void**)&ah, g_ah);
    cudaGetSymbolAddress((void**)&al, g_al);
    cudaGetSymbolAddress((void**)&wwh, g_wwh);
    cudaGetSymbolAddress((void**)&wwl, g_wwl);
    cudaGetSymbolAddress((void**)&qh, g_qh);
    cudaGetSymbolAddress((void**)&ql, g_ql);
    cudaGetSymbolAddress((void**)&kh, g_kh);
    cudaGetSymbolAddress((void**)&kl, g_kl);
    cudaGetSymbolAddress((void**)&vh, g_vh);
    cudaGetSymbolAddress((void**)&vl, g_vl);
    cudaGetSymbolAddress((void**)&oh, g_oh);
    cudaGetSymbolAddress((void**)&ol, g_ol);
    cudaGetSymbolAddress((void**)&swh, g_swh);
    cudaGetSymbolAddress((void**)&swl, g_swl);

    const int n4A = MROWS * D_ / 4;
    const int n4W = D_ * D_ / 4;
    dim3 blk(256);
    dim3 gproj(D_ / 128, MROWS / 128);   // (8, 32)

    // Q/K/V projections -> hi/lo planes
    split_fp16<<<n4A / 256, blk>>>(q, ah, al, n4A);
    split_fp16<<<n4W / 256, blk>>>(wq_w, wwh, wwl, n4W);
    proj_hl<<<gproj, blk>>>(ah, al, wwh, wwl, wq_b, qh, ql);

    split_fp16<<<n4A / 256, blk>>>(k, ah, al, n4A);
    split_fp16<<<n4W / 256, blk>>>(wk_w, wwh, wwl, n4W);
    proj_hl<<<gproj, blk>>>(ah, al, wwh, wwl, wk_b, kh, kl);

    split_fp16<<<n4A / 256, blk>>>(v, ah, al, n4A);
    split_fp16<<<n4W / 256, blk>>>(wv_w, wwh, wwl, n4W);
    proj_hl<<<gproj, blk>>>(ah, al, wwh, wwl, wv_b, vh, vl);

    // Scores (HMMA) + softmax (emits fp32 weights + hi/lo planes)
    dim3 gs(S_ / 128, S_ / 128, B_ * H_);
    scores_mma<<<gs, blk>>>(qh, ql, kh, kl, mask, wts);
    softmax_split<<<B_ * H_ * S_, blk>>>(wts, swh, swl);

    // AV (HMMA) -> attention output hi/lo planes
    dim3 ga(S_ / 128, 1, B_ * H_);
    av_mma<<<ga, blk>>>(swh, swl, vh, vl, oh, ol);

    // Final dense projection -> fp32 out
    split_fp16<<<n4W / 256, blk>>>(dw, wwh, wwl, n4W);
    proj_f32<<<gproj, blk>>>(oh, ol, wwh, wwl, db, out);
}

// round 6
// speedup vs baseline: 1.8368x; 1.0144x over previous
#include <cuda_runtime.h>
#include <cuda_fp16.h>
#include <math.h>
#include <stdint.h>

#define B_  2
#define S_  2048
#define D_  1024
#define H_  16
#define DH_ 64
#define MROWS (B_ * S_)   // 4096

// ---------------------------------------------------------------------------
// Scratch (allocation-free rule: __device__ globals)
// ---------------------------------------------------------------------------
__device__ __half g_ah[MROWS * D_];          // split staging of fp32 activations
__device__ __half g_al[MROWS * D_];
__device__ __half g_wwh[D_ * D_];            // split staging of weight matrix
__device__ __half g_wwl[D_ * D_];
__device__ __half g_qh[MROWS * D_];          // projected Q/K/V, hi/lo planes
__device__ __half g_ql[MROWS * D_];
__device__ __half g_kh[MROWS * D_];
__device__ __half g_kl[MROWS * D_];
__device__ __half g_vh[MROWS * D_];
__device__ __half g_vl[MROWS * D_];
__device__ __half g_oh[MROWS * D_];          // attention output, hi/lo planes
__device__ __half g_ol[MROWS * D_];

__device__ __forceinline__ uint32_t smem_to_u32(const void* p) {
    uint32_t addr;
    asm("{ .reg .u64 tmp; cvta.to.shared.u64 tmp, %1; cvt.u32.u64 %0, tmp; }"
        : "=r"(addr) : "l"(p));
    return addr;
}

__device__ __forceinline__ void mma16816(float* d, const uint32_t* a, const uint32_t* b) {
    asm volatile(
        "mma.sync.aligned.m16n8k16.row.col.f32.f16.f16.f32 "
        "{%0,%1,%2,%3}, {%4,%5,%6,%7}, {%8,%9}, {%0,%1,%2,%3};"
        : "+f"(d[0]), "+f"(d[1]), "+f"(d[2]), "+f"(d[3])
        : "r"(a[0]), "r"(a[1]), "r"(a[2]), "r"(a[3]), "r"(b[0]), "r"(b[1]));
}

__device__ __forceinline__ void cp_async16(uint32_t dst, const void* src) {
    asm volatile("cp.async.ca.shared.global [%0], [%1], 16;" :: "r"(dst), "l"(src));
}
#define CP_COMMIT() asm volatile("cp.async.commit_group;" ::: "memory")
#define CP_WAIT(n)  asm volatile("cp.async.wait_group %0;" :: "n"(n) : "memory")

// ---------------------------------------------------------------------------
// split_fp16: x (fp32) -> hi = fp16(x), lo = fp16(x - hi). Vectorized by 4.
// ---------------------------------------------------------------------------
__global__ void __launch_bounds__(256) split_fp16(
    const float* __restrict__ x,
    __half* __restrict__ hi,
    __half* __restrict__ lo,
    int n4)
{
    int i = blockIdx.x * 256 + threadIdx.x;
    if (i >= n4) return;
    float4 v = ((const float4*)x)[i];
    __half h0 = __float2half_rn(v.x);
    __half h1 = __float2half_rn(v.y);
    __half h2 = __float2half_rn(v.z);
    __half h3 = __float2half_rn(v.w);
    __half l0 = __float2half_rn(v.x - __half2float(h0));
    __half l1 = __float2half_rn(v.y - __half2float(h1));
    __half l2 = __float2half_rn(v.z - __half2float(h2));
    __half l3 = __float2half_rn(v.w - __half2float(h3));
    ((__half2*)hi)[i * 2 + 0] = __halves2half2(h0, h1);
    ((__half2*)hi)[i * 2 + 1] = __halves2half2(h2, h3);
    ((__half2*)lo)[i * 2 + 0] = __halves2half2(l0, l1);
    ((__half2*)lo)[i * 2 + 1] = __halves2half2(l2, l3);
}

// ---------------------------------------------------------------------------
// Shared 128x128 HMMA mainloop (split-fp16 3-term), cp.async 2-stage pipeline.
// A [128, K] stride lda (hi/lo), B [128, K] stride ldb (hi/lo), k-contiguous.
// A: ldmatrix.x4, B: ldmatrix.x2 (no trans). 8 warps (2x4), warp tile 64x32.
// Dynamic smem: 2 stages x 4 planes x PLANE halves = 81920 B.
// ---------------------------------------------------------------------------
#define SPAD 40
#define PLANE (128 * SPAD)
#define STAGE_HALVES (4 * PLANE)
#define ML_DSMEM (2 * STAGE_HALVES * 2)   // bytes

__device__ __forceinline__ void mainloop128(
    const __half* __restrict__ A0, const __half* __restrict__ A1,
    const __half* __restrict__ B0, const __half* __restrict__ B1,
    int lda, int ldb, int K, __half* sbase,
    float (&acc)[4][4][4])
{
    const int tid = threadIdx.x;
    const int wid = tid >> 5;
    const int lane = tid & 31;
    const int wm = (wid >> 2) * 64;
    const int wn = (wid & 3) * 32;

    const int a_row = (lane & 7) + ((lane >> 3) & 1) * 8;
    const int a_col = (lane >> 4) * 8;
    const int b_row = lane & 7;
    const int b_col = ((lane >> 3) & 1) * 8;

    const int lrow = tid >> 1;
    const int lcol = (tid & 1) * 16;
    const int soff = lrow * SPAD + lcol;

    const int NCH = K / 32;

    // Issue loads for chunk c into stage s
    auto issue = [&](int c, int s) {
        __half* buf = sbase + s * STAGE_HALVES;
        const uint32_t base = smem_to_u32(buf);
        const size_t ga = (size_t)lrow * lda + c * 32 + lcol;
        const size_t gw = (size_t)lrow * ldb + c * 32 + lcol;
        cp_async16(base + (uint32_t)(soff) * 2,                       A0 + ga);
        cp_async16(base + (uint32_t)(soff + 8) * 2,                   A0 + ga + 8);
        cp_async16(base + (uint32_t)(PLANE + soff) * 2,               A1 + ga);
        cp_async16(base + (uint32_t)(PLANE + soff + 8) * 2,           A1 + ga + 8);
        cp_async16(base + (uint32_t)(2 * PLANE + soff) * 2,           B0 + gw);
        cp_async16(base + (uint32_t)(2 * PLANE + soff + 8) * 2,       B0 + gw + 8);
        cp_async16(base + (uint32_t)(3 * PLANE + soff) * 2,           B1 + gw);
        cp_async16(base + (uint32_t)(3 * PLANE + soff + 8) * 2,       B1 + gw + 8);
    };

    issue(0, 0);
    CP_COMMIT();

    for (int c = 0; c < NCH; c++) {
        const int stage = c & 1;
        if (c + 1 < NCH) {
            issue(c + 1, stage ^ 1);
            CP_COMMIT();
            CP_WAIT(1);
        } else {
            CP_WAIT(0);
        }
        __syncthreads();

        __half* buf = sbase + stage * STAGE_HALVES;
        const uint32_t sA0 = smem_to_u32(buf);
        const uint32_t sA1 = sA0 + PLANE * 2;
        const uint32_t sW0 = sA0 + 2 * PLANE * 2;
        const uint32_t sW1 = sA0 + 3 * PLANE * 2;

#pragma unroll
        for (int ks = 0; ks < 2; ks++) {
            uint32_t afh[4][4], afl[4][4], bfh[4][2], bfl[4][2];
#pragma unroll
            for (int mf = 0; mf < 4; mf++) {
                uint32_t off = (uint32_t)((wm + mf * 16 + a_row) * SPAD + ks * 16 + a_col) * 2;
                asm volatile("ldmatrix.sync.aligned.m8n8.x4.shared.b16 {%0,%1,%2,%3}, [%4];"
                    : "=r"(afh[mf][0]), "=r"(afh[mf][1]), "=r"(afh[mf][2]), "=r"(afh[mf][3])
                    : "r"(sA0 + off));
                asm volatile("ldmatrix.sync.aligned.m8n8.x4.shared.b16 {%0,%1,%2,%3}, [%4];"
                    : "=r"(afl[mf][0]), "=r"(afl[mf][1]), "=r"(afl[mf][2]), "=r"(afl[mf][3])
                    : "r"(sA1 + off));
            }
#pragma unroll
            for (int nf = 0; nf < 4; nf++) {
                uint32_t off = (uint32_t)((wn + nf * 8 + b_row) * SPAD + ks * 16 + b_col) * 2;
                asm volatile("ldmatrix.sync.aligned.m8n8.x2.shared.b16 {%0,%1}, [%2];"
                    : "=r"(bfh[nf][0]), "=r"(bfh[nf][1]) : "r"(sW0 + off));
                asm volatile("ldmatrix.sync.aligned.m8n8.x2.shared.b16 {%0,%1}, [%2];"
                    : "=r"(bfl[nf][0]), "=r"(bfl[nf][1]) : "r"(sW1 + off));
            }
#pragma unroll
            for (int mf = 0; mf < 4; mf++)
#pragma unroll
                for (int nf = 0; nf < 4; nf++) {
                    mma16816(acc[mf][nf], afh[mf], bfh[nf]);
                    mma16816(acc[mf][nf], afh[mf], bfl[nf]);
                    mma16816(acc[mf][nf], afl[mf], bfh[nf]);
                }
        }
        __syncthreads();
    }
}

// ---------------------------------------------------------------------------
// proj_f32: final dense projection -> fp32 out (d_out)
// ---------------------------------------------------------------------------
__global__ void __launch_bounds__(256) proj_f32(
    const __half* __restrict__ Ah, const __half* __restrict__ Al,
    const __half* __restrict__ Wh, const __half* __restrict__ Wl,
    const float* __restrict__ bias, float* __restrict__ C)
{
    extern __shared__ __half dsm[];
    const int m0 = blockIdx.y * 128;
    const int n0 = blockIdx.x * 128;
    float acc[4][4][4] = {};
    mainloop128(Ah + (size_t)m0 * D_, Al + (size_t)m0 * D_,
                Wh + (size_t)n0 * D_, Wl + (size_t)n0 * D_,
                D_, D_, D_, dsm, acc);

    const int lane = threadIdx.x & 31;
    const int wid = threadIdx.x >> 5;
    const int wm = (wid >> 2) * 64, wn = (wid & 3) * 32;
    const int g = lane >> 2, t = lane & 3;
#pragma unroll
    for (int mf = 0; mf < 4; mf++)
#pragma unroll
        for (int nf = 0; nf < 4; nf++) {
            const int col = n0 + wn + nf * 8 + t * 2;
            const float b0 = bias[col], b1 = bias[col + 1];
            const int row = m0 + wm + mf * 16 + g;
            float2 o0, o1;
            o0.x = acc[mf][nf][0] + b0; o0.y = acc[mf][nf][1] + b1;
            o1.x = acc[mf][nf][2] + b0; o1.y = acc[mf][nf][3] + b1;
            *(float2*)&C[(size_t)row * D_ + col] = o0;
            *(float2*)&C[(size_t)(row + 8) * D_ + col] = o1;
        }
}

// ---------------------------------------------------------------------------
// proj_hl: QKV projection -> hi/lo half planes directly
// ---------------------------------------------------------------------------
__global__ void __launch_bounds__(256) proj_hl(
    const __half* __restrict__ Ah, const __half* __restrict__ Al,
    const __half* __restrict__ Wh, const __half* __restrict__ Wl,
    const float* __restrict__ bias,
    __half* __restrict__ Ch, __half* __restrict__ Cl)
{
    extern __shared__ __half dsm[];
    const int m0 = blockIdx.y * 128;
    const int n0 = blockIdx.x * 128;
    float acc[4][4][4] = {};
    mainloop128(Ah + (size_t)m0 * D_, Al + (size_t)m0 * D_,
                Wh + (size_t)n0 * D_, Wl + (size_t)n0 * D_,
                D_, D_, D_, dsm, acc);

    const int lane = threadIdx.x & 31;
    const int wid = threadIdx.x >> 5;
    const int wm = (wid >> 2) * 64, wn = (wid & 3) * 32;
    const int g = lane >> 2, t = lane & 3;
#pragma unroll
    for (int mf = 0; mf < 4; mf++)
#pragma unroll
        for (int nf = 0; nf < 4; nf++) {
            const int col = n0 + wn + nf * 8 + t * 2;
            const float b0 = bias[col], b1 = bias[col + 1];
            const int row = m0 + wm + mf * 16 + g;
            float v0 = acc[mf][nf][0] + b0, v1 = acc[mf][nf][1] + b1;
            float v2 = acc[mf][nf][2] + b0, v3 = acc[mf][nf][3] + b1;
            __half h0 = __float2half_rn(v0), h1 = __float2half_rn(v1);
            __half h2 = __float2half_rn(v2), h3 = __float2half_rn(v3);
            *(__half2*)&Ch[(size_t)row * D_ + col] = __halves2half2(h0, h1);
            *(__half2*)&Ch[(size_t)(row + 8) * D_ + col] = __halves2half2(h2, h3);
            *(__half2*)&Cl[(size_t)row * D_ + col] =
                __halves2half2(__float2half_rn(v0 - __half2float(h0)),
                               __float2half_rn(v1 - __half2float(h1)));
            *(__half2*)&Cl[(size_t)(row + 8) * D_ + col] =
                __halves2half2(__float2half_rn(v2 - __half2float(h2)),
                               __float2half_rn(v3 - __half2float(h3)));
        }
}

// ---------------------------------------------------------------------------
// scores_mma: per (b,h): Wout = mask ? scale*(Q K^T) : -inf ; K-dim = 64
// ---------------------------------------------------------------------------
__global__ void __launch_bounds__(256) scores_mma(
    const __half* __restrict__ Qh, const __half* __restrict__ Ql,
    const __half* __restrict__ Kh, const __half* __restrict__ Kl,
    const int* __restrict__ mask, float* __restrict__ Wout)
{
    extern __shared__ __half dsm[];
    const int bh = blockIdx.z;
    const int b = bh >> 4;
    const int h = bh & 15;
    const int m0 = blockIdx.y * 128;
    const int n0 = blockIdx.x * 128;

    const size_t aoff = ((size_t)b * S_ + m0) * D_ + h * DH_;
    const size_t boff = ((size_t)b * S_ + n0) * D_ + h * DH_;
    float acc[4][4][4] = {};
    mainloop128(Qh + aoff, Ql + aoff, Kh + boff, Kl + boff,
                D_, D_, DH_, dsm, acc);

    const int* mk = mask + (size_t)b * S_ * S_;
    float* C = Wout + (size_t)bh * S_ * S_;
    const int lane = threadIdx.x & 31;
    const int wid = threadIdx.x >> 5;
    const int wm = (wid >> 2) * 64, wn = (wid & 3) * 32;
    const int g = lane >> 2, t = lane & 3;
    const float scale = 0.125f;
#pragma unroll
    for (int mf = 0; mf < 4; mf++)
#pragma unroll
        for (int nf = 0; nf < 4; nf++) {
            const int col = n0 + wn + nf * 8 + t * 2;
#pragma unroll
            for (int rr = 0; rr < 2; rr++) {
                const int row = m0 + wm + mf * 16 + g + rr * 8;
                int2 mv = *(const int2*)&mk[(size_t)row * S_ + col];
                float2 o;
                o.x = mv.x ? acc[mf][nf][rr * 2 + 0] * scale : -INFINITY;
                o.y = mv.y ? acc[mf][nf][rr * 2 + 1] * scale : -INFINITY;
                *(float2*)&C[(size_t)row * S_ + col] = o;
            }
        }
}

// ---------------------------------------------------------------------------
// softmax_kernel: in-place row softmax over last dim (S=2048), 1 block/row.
// ---------------------------------------------------------------------------
__global__ void __launch_bounds__(256) softmax_kernel(float* __restrict__ Wt)
{
    const size_t row = blockIdx.x;
    float* p = Wt + row * S_;
    const int tid = threadIdx.x;

    float vals[8];
    float m = -INFINITY;
#pragma unroll
    for (int t = 0; t < 8; t++) {
        vals[t] = p[tid + t * 256];
        m = fmaxf(m, vals[t]);
    }

    __shared__ float red[256];
    red[tid] = m;
    __syncthreads();
#pragma unroll
    for (int s = 128; s > 0; s >>= 1) {
        if (tid < s) red[tid] = fmaxf(red[tid], red[tid + s]);
        __syncthreads();
    }
    m = red[0];
    __syncthreads();

    float sum = 0.0f;
#pragma unroll
    for (int t = 0; t < 8; t++) {
        vals[t] = __expf(vals[t] - m);
        sum += vals[t];
    }
    red[tid] = sum;
    __syncthreads();
#pragma unroll
    for (int s = 128; s > 0; s >>= 1) {
        if (tid < s) red[tid] += red[tid + s];
        __syncthreads();
    }
    const float inv = 1.0f / red[0];

#pragma unroll
    for (int t = 0; t < 8; t++)
        p[tid + t * 256] = vals[t] * inv;
}

// ---------------------------------------------------------------------------
// av_mma: per (b,h): O[m, h*64+n] = sum_k W[m,k] V[k, h*64+n]; out as hi/lo.
// Weights read as fp32, split to hi/lo on-the-fly into SMEM.
// BM=128, BN=64, BK=32. 8 warps (4m x 2n), warp tile 32x32.
// A: ldmatrix.x4. B: V[k][n] n-contig -> ldmatrix.x2.trans.
// ---------------------------------------------------------------------------
#define AV_SPAD_A 40
#define AV_SPAD_B 72

__global__ void __launch_bounds__(256) av_mma(
    const float* __restrict__ Wt,
    const __half* __restrict__ Vh, const __half* __restrict__ Vl,
    __half* __restrict__ Oh, __half* __restrict__ Ol)
{
    __shared__ __half sA0p[128 * AV_SPAD_A], sA1p[128 * AV_SPAD_A];
    __shared__ __half sB0p[32 * AV_SPAD_B], sB1p[32 * AV_SPAD_B];

    const int bh = blockIdx.z;
    const int b = bh >> 4;
    const int h = bh & 15;
    const int m0 = blockIdx.x * 128;

    const float* A = Wt + (size_t)bh * S_ * S_ + (size_t)m0 * S_;
    const __half* B0 = Vh + (size_t)b * S_ * D_ + h * DH_;
    const __half* B1 = Vl + (size_t)b * S_ * D_ + h * DH_;

    const int tid = threadIdx.x;
    const int wid = tid >> 5;
    const int lane = tid & 31;
    const int wm = (wid >> 1) * 32;
    const int wn = (wid & 1) * 32;

    float acc[2][4][4] = {};

    const uint32_t sA0 = smem_to_u32(sA0p);
    const uint32_t sA1 = smem_to_u32(sA1p);
    const uint32_t sB0 = smem_to_u32(sB0p);
    const uint32_t sB1 = smem_to_u32(sB1p);

    const int a_row = (lane & 7) + ((lane >> 3) & 1) * 8;
    const int a_col = (lane >> 4) * 8;
    const int bt_row = (lane & 7) + ((lane >> 3) & 1) * 8;

    // A (fp32): 128x32 = 1024 float4; 4 per thread. B: 256 uint4; 1 per thread.
    const int br = tid >> 3, bc = (tid & 7) * 8;

    for (int k0 = 0; k0 < S_; k0 += 32) {
        __syncthreads();
#pragma unroll
        for (int gq = 0; gq < 4; gq++) {
            const int idx = gq * 256 + tid;
            const int r = idx >> 3;
            const int cc = (idx & 7) * 4;
            float4 v = *(const float4*)&A[(size_t)r * S_ + k0 + cc];
            __half h0 = __float2half_rn(v.x), h1 = __float2half_rn(v.y);
            __half h2 = __float2half_rn(v.z), h3 = __float2half_rn(v.w);
            const int so = r * AV_SPAD_A + cc;
            *(__half2*)&sA0p[so]     = __halves2half2(h0, h1);
            *(__half2*)&sA0p[so + 2] = __halves2half2(h2, h3);
            *(__half2*)&sA1p[so] =
                __halves2half2(__float2half_rn(v.x - __half2float(h0)),
                               __float2half_rn(v.y - __half2float(h1)));
            *(__half2*)&sA1p[so + 2] =
                __halves2half2(__float2half_rn(v.z - __half2float(h2)),
                               __float2half_rn(v.w - __half2float(h3)));
        }
        {
            const size_t gb = (size_t)(k0 + br) * D_ + bc;
            *(uint4*)&sB0p[br * AV_SPAD_B + bc] = *(const uint4*)&B0[gb];
            *(uint4*)&sB1p[br * AV_SPAD_B + bc] = *(const uint4*)&B1[gb];
        }
        __syncthreads();

#pragma unroll
        for (int ks = 0; ks < 2; ks++) {
            uint32_t afh[2][4], afl[2][4], bfh[4][2], bfl[4][2];
#pragma unroll
            for (int mf = 0; mf < 2; mf++) {
                uint32_t off = (uint32_t)((wm + mf * 16 + a_row) * AV_SPAD_A + ks * 16 + a_col) * 2;
                asm volatile("ldmatrix.sync.aligned.m8n8.x4.shared.b16 {%0,%1,%2,%3}, [%4];"
                    : "=r"(afh[mf][0]), "=r"(afh[mf][1]), "=r"(afh[mf][2]), "=r"(afh[mf][3])
                    : "r"(sA0 + off));
                asm volatile("ldmatrix.sync.aligned.m8n8.x4.shared.b16 {%0,%1,%2,%3}, [%4];"
                    : "=r"(afl[mf][0]), "=r"(afl[mf][1]), "=r"(afl[mf][2]), "=r"(afl[mf][3])
                    : "r"(sA1 + off));
            }
#pragma unroll
            for (int nf = 0; nf < 4; nf++) {
                uint32_t off = (uint32_t)((ks * 16 + bt_row) * AV_SPAD_B + wn + nf * 8) * 2;
                asm volatile("ldmatrix.sync.aligned.m8n8.x2.trans.shared.b16 {%0,%1}, [%2];"
                    : "=r"(bfh[nf][0]), "=r"(bfh[nf][1]) : "r"(sB0 + off));
                asm volatile("ldmatrix.sync.aligned.m8n8.x2.trans.shared.b16 {%0,%1}, [%2];"
                    : "=r"(bfl[nf][0]), "=r"(bfl[nf][1]) : "r"(sB1 + off));
            }
#pragma unroll
            for (int mf = 0; mf < 2; mf++)
#pragma unroll
                for (int nf = 0; nf < 4; nf++) {
                    mma16816(acc[mf][nf], afh[mf], bfh[nf]);
                    mma16816(acc[mf][nf], afh[mf], bfl[nf]);
                    mma16816(acc[mf][nf], afl[mf], bfh[nf]);
                }
        }
    }

    const int g = lane >> 2, t = lane & 3;
#pragma unroll
    for (int mf = 0; mf < 2; mf++)
#pragma unroll
        for (int nf = 0; nf < 4; nf++) {
            const int col = h * DH_ + wn + nf * 8 + t * 2;
#pragma unroll
            for (int rr = 0; rr < 2; rr++) {
                const int row = m0 + wm + mf * 16 + g + rr * 8;
                const size_t o = ((size_t)b * S_ + row) * D_ + col;
                float v0 = acc[mf][nf][rr * 2 + 0];
                float v1 = acc[mf][nf][rr * 2 + 1];
                __half h0 = __float2half_rn(v0), h1 = __float2half_rn(v1);
                *(__half2*)&Oh[o] = __halves2half2(h0, h1);
                *(__half2*)&Ol[o] =
                    __halves2half2(__float2half_rn(v0 - __half2float(h0)),
                                   __float2half_rn(v1 - __half2float(h1)));
            }
        }
}

// ---------------------------------------------------------------------------
extern "C" void kernel_launch(void* const* d_in, const int* in_sizes, int n_in,
                              void* d_out, int out_size)
{
    const float* q      = (const float*)d_in[0];
    const float* k      = (const float*)d_in[1];
    const float* v      = (const float*)d_in[2];
    const int*   mask   = (const int*)  d_in[3];
    const float* wq_w   = (const float*)d_in[4];
    const float* wq_b   = (const float*)d_in[5];
    const float* wk_w   = (const float*)d_in[6];
    const float* wk_b   = (const float*)d_in[7];
    const float* wv_w   = (const float*)d_in[8];
    const float* wv_b   = (const float*)d_in[9];
    const float* dw     = (const float*)d_in[10];
    const float* db     = (const float*)d_in[11];

    float* out = (float*)d_out;                        // [B,S,D]
    float* wts = out + (size_t)B_ * S_ * D_;           // [B,H,S,S]

    __half *ah, *al, *wwh, *wwl, *qh, *ql, *kh, *kl, *vh, *vl, *oh, *ol;
    cudaGetSymbolAddress((void**)&ah, g_ah);
    cudaGetSymbolAddress((void**)&al, g_al);
    cudaGetSymbolAddress((void**)&wwh, g_wwh);
    cudaGetSymbolAddress((void**)&wwl, g_wwl);
    cudaGetSymbolAddress((void**)&qh, g_qh);
    cudaGetSymbolAddress((void**)&ql, g_ql);
    cudaGetSymbolAddress((void**)&kh, g_kh);
    cudaGetSymbolAddress((void**)&kl, g_kl);
    cudaGetSymbolAddress((void**)&vh, g_vh);
    cudaGetSymbolAddress((void**)&vl, g_vl);
    cudaGetSymbolAddress((void**)&oh, g_oh);
    cudaGetSymbolAddress((void**)&ol, g_ol);

    cudaFuncSetAttribute(proj_hl,  cudaFuncAttributeMaxDynamicSharedMemorySize, ML_DSMEM);
    cudaFuncSetAttribute(proj_f32, cudaFuncAttributeMaxDynamicSharedMemorySize, ML_DSMEM);
    cudaFuncSetAttribute(scores_mma, cudaFuncAttributeMaxDynamicSharedMemorySize, ML_DSMEM);

    const int n4A = MROWS * D_ / 4;
    const int n4W = D_ * D_ / 4;
    dim3 blk(256);
    dim3 gproj(D_ / 128, MROWS / 128);   // (8, 32)

    // Q/K/V projections -> hi/lo planes
    split_fp16<<<n4A / 256, blk>>>(q, ah, al, n4A);
    split_fp16<<<n4W / 256, blk>>>(wq_w, wwh, wwl, n4W);
    proj_hl<<<gproj, blk, ML_DSMEM>>>(ah, al, wwh, wwl, wq_b, qh, ql);

    split_fp16<<<n4A / 256, blk>>>(k, ah, al, n4A);
    split_fp16<<<n4W / 256, blk>>>(wk_w, wwh, wwl, n4W);
    proj_hl<<<gproj, blk, ML_DSMEM>>>(ah, al, wwh, wwl, wk_b, kh, kl);

    split_fp16<<<n4A / 256, blk>>>(v, ah, al, n4A);
    split_fp16<<<n4W / 256, blk>>>(wv_w, wwh, wwl, n4W);
    proj_hl<<<gproj, blk, ML_DSMEM>>>(ah, al, wwh, wwl, wv_b, vh, vl);

    // Scores (HMMA) + softmax (fp32 in/out)
    dim3 gs(S_ / 128, S_ / 128, B_ * H_);
    scores_mma<<<gs, blk, ML_DSMEM>>>(qh, ql, kh, kl, mask, wts);
    softmax_kernel<<<B_ * H_ * S_, blk>>>(wts);

    // AV (HMMA, fp32 weights split on-the-fly) -> attention output hi/lo
    dim3 ga(S_ / 128, 1, B_ * H_);
    av_mma<<<ga, blk>>>(wts, vh, vl, oh, ol);

    // Final dense projection -> fp32 out
    split_fp16<<<n4W / 256, blk>>>(dw, wwh, wwl, n4W);
    proj_f32<<<gproj, blk, ML_DSMEM>>>(oh, ol, wwh, wwl, db, out);
}